// round 5
// baseline (speedup 1.0000x reference)
#include <cuda_runtime.h>
#include <cstdint>

// ---------------------------------------------------------------------------
// Problem constants
// ---------------------------------------------------------------------------
#define BB 32
#define LL 256
#define SS 128
#define AA 16
#define RR 4
#define M_TOK 8192        // B*L
#define K0 132            // S + R
#define K0P 136           // padded to /8
#define D1 2112
#define D2 4224
#define D3 8448
#define D4 4224
#define D5 64

// SMEM tile geometry
#define SSTRIDE 136       // 128 + 8 pad  (k-major [16][136])
#define SA (16 * SSTRIDE) // 2176 floats per (region)
#define SMB (2 * 4 * SA * 4)  // 2 buf * 4 regions(Ah,Al,Bh,Bl) * SA floats * 4B = 69632

// ---------------------------------------------------------------------------
// Scratch (static device globals; no allocation at runtime)
// ---------------------------------------------------------------------------
__device__ float g_x0[M_TOK * K0P];
__device__ float g_a1[M_TOK * D1];
__device__ float g_a2[M_TOK * D2];
__device__ float g_a3[M_TOK * D3];
__device__ float g_a4[M_TOK * D4];

// ---------------------------------------------------------------------------
// Helpers
// ---------------------------------------------------------------------------
__device__ __forceinline__ unsigned f2tf(float x) {
    unsigned y;
    asm("cvt.rna.tf32.f32 %0, %1;" : "=r"(y) : "f"(x));
    return y;
}

__device__ __forceinline__ void mma8(float* c, const unsigned* a, const unsigned* b) {
    asm volatile(
        "mma.sync.aligned.m16n8k8.row.col.f32.tf32.tf32.f32 "
        "{%0,%1,%2,%3},{%4,%5,%6,%7},{%8,%9},{%0,%1,%2,%3};\n"
        : "+f"(c[0]), "+f"(c[1]), "+f"(c[2]), "+f"(c[3])
        : "r"(a[0]), "r"(a[1]), "r"(a[2]), "r"(a[3]), "r"(b[0]), "r"(b[1]));
}

// ---------------------------------------------------------------------------
// Concat: X0[row, 0:128] = state, [128:132] = preference, [132:136] = 0
// ---------------------------------------------------------------------------
__global__ void k_concat(const float* __restrict__ st, const float* __restrict__ pf,
                         float* __restrict__ x0) {
    int idx = blockIdx.x * blockDim.x + threadIdx.x;
    if (idx >= M_TOK * K0P) return;
    int row = idx / K0P;
    int c   = idx - row * K0P;
    float v;
    if (c < SS)        v = st[row * SS + c];
    else if (c < K0)   v = pf[row * RR + (c - SS)];
    else               v = 0.0f;
    x0[idx] = v;
}

// ---------------------------------------------------------------------------
// Generic GEMM: C[M,N] = act(A[M,KA(used rows:KW for W)] * W[KW,N] + bias)
// 3xTF32 split, mma.sync m16n8k8. Tile 128x128, BK=16, 256 threads, 8 warps
// (4x2), warp tile 32x64. Double-buffered SMEM (dynamic, 69632 B).
// ---------------------------------------------------------------------------
template <bool RELU>
__global__ __launch_bounds__(256, 1)
void k_gemm(const float* __restrict__ A, const float* __restrict__ W,
            const float* __restrict__ bias, float* __restrict__ C,
            int N, int KA, int KW) {
    extern __shared__ float sm[];

    const int tid  = threadIdx.x;
    const int bm   = blockIdx.y * 128;
    const int n0   = blockIdx.x * 128;
    const int lane = tid & 31;
    const int wid  = tid >> 5;
    const int wm   = wid & 3;          // warp row  (0..3) -> 32 rows each
    const int wn   = wid >> 2;         // warp col  (0..1) -> 64 cols each
    const int grp  = lane >> 2;
    const int tig  = lane & 3;

    // global-load thread mapping
    const int arow = tid >> 1, aq = tid & 1;     // A: 128 rows x 16 k, 8 floats/thr
    const int wrow = tid >> 4, wseg = tid & 15;  // W: 16 rows x 128 n, 8 floats/thr

    const float* Abase = A + (long)(bm + arow) * KA + aq * 8;
    const float* Wbase = W + (long)wrow * N + n0 + wseg * 8;
    const bool wc0 = (n0 + wseg * 8) < N;
    const bool wc1 = (n0 + wseg * 8 + 4) < N;

    float c[2][8][4];
#pragma unroll
    for (int mt = 0; mt < 2; mt++)
#pragma unroll
        for (int nt = 0; nt < 8; nt++)
#pragma unroll
            for (int j = 0; j < 4; j++) c[mt][nt][j] = 0.0f;

    float4 va0, va1, vw0, vw1;
    const float4 z4 = make_float4(0.f, 0.f, 0.f, 0.f);

    auto fetch = [&](int k0) {
        int ka = k0 + aq * 8;
        va0 = (ka < KA)     ? *(const float4*)(Abase + k0)     : z4;
        va1 = (ka + 4 < KA) ? *(const float4*)(Abase + k0 + 4) : z4;
        int kw = k0 + wrow;
        const float* wp = Wbase + (long)k0 * N;
        bool kok = kw < KW;
        vw0 = (kok && wc0) ? *(const float4*)(wp)     : z4;
        vw1 = (kok && wc1) ? *(const float4*)(wp + 4) : z4;
    };

    auto sstore = [&](int buf) {
        float* Ah = sm + buf * (4 * SA);
        float* Al = Ah + SA;
        float* Bh = Ah + 2 * SA;
        float* Bl = Ah + 3 * SA;
        float av[8] = {va0.x, va0.y, va0.z, va0.w, va1.x, va1.y, va1.z, va1.w};
#pragma unroll
        for (int j = 0; j < 8; j++) {
            float x = av[j];
            unsigned h = f2tf(x);
            float hf = __uint_as_float(h);
            unsigned lo = f2tf(x - hf);
            int off = (aq * 8 + j) * SSTRIDE + arow;
            Ah[off] = hf;
            Al[off] = __uint_as_float(lo);
        }
        float wv[8] = {vw0.x, vw0.y, vw0.z, vw0.w, vw1.x, vw1.y, vw1.z, vw1.w};
        float hib[8], lob[8];
#pragma unroll
        for (int j = 0; j < 8; j++) {
            float x = wv[j];
            unsigned h = f2tf(x);
            float hf = __uint_as_float(h);
            unsigned lo = f2tf(x - hf);
            hib[j] = hf;
            lob[j] = __uint_as_float(lo);
        }
        int boff = wrow * SSTRIDE + wseg * 8;
        *(float4*)(Bh + boff)     = make_float4(hib[0], hib[1], hib[2], hib[3]);
        *(float4*)(Bh + boff + 4) = make_float4(hib[4], hib[5], hib[6], hib[7]);
        *(float4*)(Bl + boff)     = make_float4(lob[0], lob[1], lob[2], lob[3]);
        *(float4*)(Bl + boff + 4) = make_float4(lob[4], lob[5], lob[6], lob[7]);
    };

    auto compute = [&](int buf) {
        const float* Ah = sm + buf * (4 * SA);
        const float* Al = Ah + SA;
        const float* Bh = Ah + 2 * SA;
        const float* Bl = Ah + 3 * SA;
#pragma unroll
        for (int kk = 0; kk < 16; kk += 8) {
            unsigned ah[2][4], al[2][4], bh[8][2], bl[8][2];
            const int kb = (kk + tig) * SSTRIDE;
#pragma unroll
            for (int mt = 0; mt < 2; mt++) {
                int r0 = wm * 32 + mt * 16 + grp;
                ah[mt][0] = __float_as_uint(Ah[kb + r0]);
                ah[mt][1] = __float_as_uint(Ah[kb + r0 + 8]);
                ah[mt][2] = __float_as_uint(Ah[kb + 4 * SSTRIDE + r0]);
                ah[mt][3] = __float_as_uint(Ah[kb + 4 * SSTRIDE + r0 + 8]);
                al[mt][0] = __float_as_uint(Al[kb + r0]);
                al[mt][1] = __float_as_uint(Al[kb + r0 + 8]);
                al[mt][2] = __float_as_uint(Al[kb + 4 * SSTRIDE + r0]);
                al[mt][3] = __float_as_uint(Al[kb + 4 * SSTRIDE + r0 + 8]);
            }
#pragma unroll
            for (int nt = 0; nt < 8; nt++) {
                int c0 = wn * 64 + nt * 8 + grp;
                bh[nt][0] = __float_as_uint(Bh[kb + c0]);
                bh[nt][1] = __float_as_uint(Bh[kb + 4 * SSTRIDE + c0]);
                bl[nt][0] = __float_as_uint(Bl[kb + c0]);
                bl[nt][1] = __float_as_uint(Bl[kb + 4 * SSTRIDE + c0]);
            }
#pragma unroll
            for (int mt = 0; mt < 2; mt++)
#pragma unroll
                for (int nt = 0; nt < 8; nt++) {
                    mma8(c[mt][nt], ah[mt], bh[nt]);   // hi*hi
                    mma8(c[mt][nt], al[mt], bh[nt]);   // lo*hi
                    mma8(c[mt][nt], ah[mt], bl[nt]);   // hi*lo
                }
        }
    };

    const int T = (KA + 15) >> 4;
    fetch(0);
    sstore(0);
    __syncthreads();
    int buf = 0;
    for (int t = 0; t < T; ++t) {
        if (t + 1 < T) fetch((t + 1) * 16);
        compute(buf);
        if (t + 1 < T) {
            sstore(buf ^ 1);
            __syncthreads();
            buf ^= 1;
        }
    }

    // epilogue: bias (+ relu), guarded stores
#pragma unroll
    for (int mt = 0; mt < 2; mt++) {
        int r = bm + wm * 32 + mt * 16 + grp;
#pragma unroll
        for (int nt = 0; nt < 8; nt++) {
            int col = n0 + wn * 64 + nt * 8 + tig * 2;
            if (col < N) {
                float bv0 = bias[col], bv1 = bias[col + 1];
                float v0 = c[mt][nt][0] + bv0;
                float v1 = c[mt][nt][1] + bv1;
                float v2 = c[mt][nt][2] + bv0;
                float v3 = c[mt][nt][3] + bv1;
                if (RELU) {
                    v0 = fmaxf(v0, 0.f); v1 = fmaxf(v1, 0.f);
                    v2 = fmaxf(v2, 0.f); v3 = fmaxf(v3, 0.f);
                }
                C[(long)r * N + col]           = v0;
                C[(long)r * N + col + 1]       = v1;
                C[(long)(r + 8) * N + col]     = v2;
                C[(long)(r + 8) * N + col + 1] = v3;
            }
        }
    }
}

// ---------------------------------------------------------------------------
// _H epilogue (exact replication of the reference index gymnastics).
// reQ[n=b'*16+a, l2, r2] = Q[perm[b'], 4*(l2%64)+r2, a, l2/64]
// perm[b'] = (b'/4) + 8*(b'%4);  candidates for batch i: n=(64*i+k) mod 512
// inds = first-argmax over k of dot(reQ_row, w[i,l2,:]);
// output position = stable rank of (inds, l2) within batch i.
// ---------------------------------------------------------------------------
__global__ void k_h(const float* __restrict__ q, const float* __restrict__ w,
                    float* __restrict__ hq) {
    const int i  = blockIdx.x;   // 0..31
    const int l2 = threadIdx.x;  // 0..255
    __shared__ int   s_ind[LL];
    __shared__ float s_sel[LL * 4];

    const int rsel = l2 >> 6;            // l2 / 64  (original r component)
    const int lb   = (l2 & 63) * 4;      // source l base

    const float w0 = w[(i * LL + l2) * RR + 0];
    const float w1 = w[(i * LL + l2) * RR + 1];
    const float w2 = w[(i * LL + l2) * RR + 2];
    const float w3 = w[(i * LL + l2) * RR + 3];

    float best = -3.402823466e38f;
    int bk = 0;
    const int nb = (64 * i) & 511;
    for (int k = 0; k < 64; ++k) {
        int n  = (nb + k) & 511;
        int bp = n >> 4, a = n & 15;
        int sb = (bp >> 2) + ((bp & 3) << 3);    // perm
        const float* qp = q + ((long)(sb * LL + lb) * AA + a) * RR + rsel;
        float u = qp[0] * w0 + qp[64] * w1 + qp[128] * w2 + qp[192] * w3;
        if (u > best) { best = u; bk = k; }      // strict > : first-max, matches argmax
    }
    s_ind[l2] = bk;
    {
        int n  = (nb + bk) & 511;
        int bp = n >> 4, a = n & 15;
        int sb = (bp >> 2) + ((bp & 3) << 3);
        const float* qp = q + ((long)(sb * LL + lb) * AA + a) * RR + rsel;
        s_sel[l2 * 4 + 0] = qp[0];
        s_sel[l2 * 4 + 1] = qp[64];
        s_sel[l2 * 4 + 2] = qp[128];
        s_sel[l2 * 4 + 3] = qp[192];
    }
    __syncthreads();

    // stable rank of (key, l2)
    int key = bk, pos = 0;
    for (int j = 0; j < LL; ++j) {
        int kj = s_ind[j];
        pos += (kj < key) || (kj == key && j < l2);
    }
    float* o = hq + (long)(i * LL + pos) * 4;
    o[0] = s_sel[l2 * 4 + 0];
    o[1] = s_sel[l2 * 4 + 1];
    o[2] = s_sel[l2 * 4 + 2];
    o[3] = s_sel[l2 * 4 + 3];
}

// ---------------------------------------------------------------------------
// Launch
// ---------------------------------------------------------------------------
extern "C" void kernel_launch(void* const* d_in, const int* in_sizes, int n_in,
                              void* d_out, int out_size) {
    const float* state = (const float*)d_in[0];
    const float* pref  = (const float*)d_in[1];
    // d_in[2] = w_num (constant 4, unused)
    const float* W1 = (const float*)d_in[3];
    const float* b1 = (const float*)d_in[4];
    const float* W2 = (const float*)d_in[5];
    const float* b2 = (const float*)d_in[6];
    const float* W3 = (const float*)d_in[7];
    const float* b3 = (const float*)d_in[8];
    const float* W4 = (const float*)d_in[9];
    const float* b4 = (const float*)d_in[10];
    const float* W5 = (const float*)d_in[11];
    const float* b5 = (const float*)d_in[12];

    float* out = (float*)d_out;
    float* hq  = out;                        // [8192, 4]
    float* q   = out + BB * LL * RR;         // [32, 256, 16, 4]

    float *x0, *a1, *a2, *a3, *a4;
    cudaGetSymbolAddress((void**)&x0, g_x0);
    cudaGetSymbolAddress((void**)&a1, g_a1);
    cudaGetSymbolAddress((void**)&a2, g_a2);
    cudaGetSymbolAddress((void**)&a3, g_a3);
    cudaGetSymbolAddress((void**)&a4, g_a4);

    cudaFuncSetAttribute(k_gemm<true>,  cudaFuncAttributeMaxDynamicSharedMemorySize, SMB);
    cudaFuncSetAttribute(k_gemm<false>, cudaFuncAttributeMaxDynamicSharedMemorySize, SMB);

    k_concat<<<(M_TOK * K0P + 255) / 256, 256>>>(state, pref, x0);

    {
        dim3 g((D1 + 127) / 128, M_TOK / 128);
        k_gemm<true><<<g, 256, SMB>>>(x0, W1, b1, a1, D1, K0P, K0);
    }
    {
        dim3 g((D2 + 127) / 128, M_TOK / 128);
        k_gemm<true><<<g, 256, SMB>>>(a1, W2, b2, a2, D2, D1, D1);
    }
    {
        dim3 g((D3 + 127) / 128, M_TOK / 128);
        k_gemm<true><<<g, 256, SMB>>>(a2, W3, b3, a3, D3, D2, D2);
    }
    {
        dim3 g((D4 + 127) / 128, M_TOK / 128);
        k_gemm<true><<<g, 256, SMB>>>(a3, W4, b4, a4, D4, D3, D3);
    }
    {
        dim3 g(1, M_TOK / 128);
        k_gemm<false><<<g, 256, SMB>>>(a4, W5, b5, q, D5, D4, D4);
    }

    k_h<<<BB, LL>>>(q, pref, hq);
}

// round 7
// speedup vs baseline: 2.0010x; 2.0010x over previous
#include <cuda_runtime.h>
#include <cstdint>

// ---------------------------------------------------------------------------
// Problem constants
// ---------------------------------------------------------------------------
#define BB 32
#define LL 256
#define SS 128
#define AA 16
#define RR 4
#define M_TOK 8192        // B*L
#define K0 132            // S + R
#define K0P 136           // padded to /8
#define D1 2112
#define D2 4224
#define D3 8448
#define D4 4224
#define D5 64

// GEMM geometry: CTA 128x128, BK=16, 8 warps (4x2) of 32x64, raw-f32 smem,
// split-to-tf32 at read time, 4-stage cp.async pipeline, 2 CTAs/SM.
#define BK 16
#define A_STRIDE 20                      // floats per A row (16 + 4 pad)
#define B_STRIDE 136                     // floats per B k-row (128 + 8 pad)
#define A_BYTES (128 * A_STRIDE * 4)     // 10240
#define B_BYTES (BK * B_STRIDE * 4)      // 8704
#define STAGE_BYTES (A_BYTES + B_BYTES)  // 18944
#define NSTAGE 4
#define SMB (NSTAGE * STAGE_BYTES)       // 75776

// ---------------------------------------------------------------------------
// Scratch (static device globals; no allocation at runtime)
// ---------------------------------------------------------------------------
__device__ float g_x0[M_TOK * K0P];
__device__ float g_a1[M_TOK * D1];
__device__ float g_a2[M_TOK * D2];
__device__ float g_a3[M_TOK * D3];
__device__ float g_a4[M_TOK * D4];

// ---------------------------------------------------------------------------
// Helpers
// ---------------------------------------------------------------------------
__device__ __forceinline__ uint32_t smem_u32(const void* p) {
    uint32_t a;
    asm("{ .reg .u64 t; cvta.to.shared.u64 t, %1; cvt.u32.u64 %0, t; }" : "=r"(a) : "l"(p));
    return a;
}

__device__ __forceinline__ void cp16(uint32_t dst, const void* src, int pred16) {
    asm volatile("cp.async.cg.shared.global [%0], [%1], 16, %2;"
                 :: "r"(dst), "l"(src), "r"(pred16) : "memory");
}
#define CP_COMMIT() asm volatile("cp.async.commit_group;" ::: "memory")
#define CP_WAIT2()  asm volatile("cp.async.wait_group 2;" ::: "memory")

// split fp32 -> exact tf32 hi (mask-truncate) + fp32 residual lo
__device__ __forceinline__ void split(float x, float& hi, float& lo) {
    hi = __uint_as_float(__float_as_uint(x) & 0xFFFFE000u);
    lo = x - hi;
}

__device__ __forceinline__ void mma8(float* c, const float* a, const float* b) {
    asm volatile(
        "mma.sync.aligned.m16n8k8.row.col.f32.tf32.tf32.f32 "
        "{%0,%1,%2,%3},{%4,%5,%6,%7},{%8,%9},{%0,%1,%2,%3};\n"
        : "+f"(c[0]), "+f"(c[1]), "+f"(c[2]), "+f"(c[3])
        : "r"(__float_as_uint(a[0])), "r"(__float_as_uint(a[1])),
          "r"(__float_as_uint(a[2])), "r"(__float_as_uint(a[3])),
          "r"(__float_as_uint(b[0])), "r"(__float_as_uint(b[1])));
}

// ---------------------------------------------------------------------------
// Concat: X0[row, 0:128] = state, [128:132] = preference, [132:136] = 0
// ---------------------------------------------------------------------------
__global__ void k_concat(const float* __restrict__ st, const float* __restrict__ pf,
                         float* __restrict__ x0) {
    int idx = blockIdx.x * blockDim.x + threadIdx.x;
    if (idx >= M_TOK * K0P) return;
    int row = idx / K0P;
    int c   = idx - row * K0P;
    float v;
    if (c < SS)        v = st[row * SS + c];
    else if (c < K0)   v = pf[row * RR + (c - SS)];
    else               v = 0.0f;
    x0[idx] = v;
}

// ---------------------------------------------------------------------------
// GEMM: C[M,N] = act(A[M,KA] @ W[KW,N] + bias)   (3xTF32, mma.sync)
// ---------------------------------------------------------------------------
template <bool RELU>
__global__ __launch_bounds__(256, 2)
void k_gemm(const float* __restrict__ A, const float* __restrict__ W,
            const float* __restrict__ bias, float* __restrict__ C,
            int N, int KA, int KW)
{
    extern __shared__ char smem[];
    const uint32_t sb = smem_u32(smem);

    const int tid  = threadIdx.x;
    const int bm   = blockIdx.y * 128;
    const int n0   = blockIdx.x * 128;
    const int lane = tid & 31;
    const int wid  = tid >> 5;
    const int wm   = wid & 3;          // 0..3 -> 32 rows each
    const int wn   = wid >> 2;         // 0..1 -> 64 cols each
    const int grp  = lane >> 2;
    const int tig  = lane & 3;

    // ---- cp.async load mappings ----
    // A: 128 rows x 16k. 512 16B-chunks; thread -> row tid>>1, chunks 2*(tid&1), +1
    const int a_row = tid >> 1;
    const int a_c0  = (tid & 1) * 2;        // chunk index (of 4 per row)
    // B: 16 krows x 128n. 512 chunks; thread -> krow tid>>4, n chunks (tid&15), +16
    const int b_kr  = tid >> 4;
    const int b_nf  = (tid & 15) * 4;       // n offset of first chunk

    const long a_rowbase = (long)(bm + a_row) * KA;
    const int  n_ok0 = (n0 + b_nf)      < N ? 16 : 0;
    const int  n_ok1 = (n0 + b_nf + 64) < N ? 16 : 0;

    const int T = (KA + BK - 1) >> 4;

    auto load_stage = [&](int t, int slot) {
        uint32_t st = sb + slot * STAGE_BYTES;
        // A
        {
            int kg0 = t * BK + a_c0 * 4;
            uint32_t d = st + (a_row * A_STRIDE + a_c0 * 4) * 4;
#pragma unroll
            for (int u = 0; u < 2; u++) {
                int kg = kg0 + u * 4;
                int sz = (kg < KA) ? 16 : 0;
                int kc = (kg < KA) ? kg : 0;
                cp16(d + u * 16, A + a_rowbase + kc, sz);
            }
        }
        // B
        {
            int kr = t * BK + b_kr;
            int kok = kr < KW;
            long rb = (long)(kok ? kr : 0) * N + n0;
            uint32_t d = st + A_BYTES + (b_kr * B_STRIDE + b_nf) * 4;
            cp16(d,       W + rb + b_nf,      kok ? n_ok0 : 0);
            cp16(d + 256, W + rb + b_nf + 64, kok ? n_ok1 : 0);
        }
    };

    float c[2][8][4];
#pragma unroll
    for (int mt = 0; mt < 2; mt++)
#pragma unroll
        for (int nt = 0; nt < 8; nt++)
#pragma unroll
            for (int j = 0; j < 4; j++) c[mt][nt][j] = 0.0f;

    // prologue: stages 0..2
#pragma unroll
    for (int s = 0; s < NSTAGE - 1; s++) {
        if (s < T) load_stage(s, s);
        CP_COMMIT();
    }

    for (int t = 0; t < T; t++) {
        CP_WAIT2();
        __syncthreads();
        {
            int lt = t + NSTAGE - 1;
            if (lt < T) load_stage(lt, lt & (NSTAGE - 1));
            CP_COMMIT();
        }
        const int slot = t & (NSTAGE - 1);
        const float* As = (const float*)(smem + slot * STAGE_BYTES);
        const float* Bs = (const float*)(smem + slot * STAGE_BYTES + A_BYTES);

#pragma unroll
        for (int kk = 0; kk < BK; kk += 8) {
            float ah[2][4], al[2][4];
#pragma unroll
            for (int mt = 0; mt < 2; mt++) {
                int rb = (wm * 32 + mt * 16 + grp) * A_STRIDE + kk + tig;
                split(As[rb],                  ah[mt][0], al[mt][0]);
                split(As[rb + 8 * A_STRIDE],   ah[mt][1], al[mt][1]);
                split(As[rb + 4],              ah[mt][2], al[mt][2]);
                split(As[rb + 8 * A_STRIDE+4], ah[mt][3], al[mt][3]);
            }
#pragma unroll
            for (int nt = 0; nt < 8; nt++) {
                int cb = wn * 64 + nt * 8 + grp;
                float bh[2], bl[2];
                split(Bs[(kk + tig) * B_STRIDE + cb],     bh[0], bl[0]);
                split(Bs[(kk + tig + 4) * B_STRIDE + cb], bh[1], bl[1]);
#pragma unroll
                for (int mt = 0; mt < 2; mt++) {
                    mma8(c[mt][nt], ah[mt], bh);   // hi*hi
                    mma8(c[mt][nt], al[mt], bh);   // lo*hi
                    mma8(c[mt][nt], ah[mt], bl);   // hi*lo
                }
            }
        }
    }

    // epilogue: bias (+ relu), guarded stores
#pragma unroll
    for (int mt = 0; mt < 2; mt++) {
        int r = bm + wm * 32 + mt * 16 + grp;
#pragma unroll
        for (int nt = 0; nt < 8; nt++) {
            int col = n0 + wn * 64 + nt * 8 + tig * 2;
            if (col < N) {
                float bv0 = bias[col], bv1 = bias[col + 1];
                float v0 = c[mt][nt][0] + bv0;
                float v1 = c[mt][nt][1] + bv1;
                float v2 = c[mt][nt][2] + bv0;
                float v3 = c[mt][nt][3] + bv1;
                if (RELU) {
                    v0 = fmaxf(v0, 0.f); v1 = fmaxf(v1, 0.f);
                    v2 = fmaxf(v2, 0.f); v3 = fmaxf(v3, 0.f);
                }
                C[(long)r * N + col]           = v0;
                C[(long)r * N + col + 1]       = v1;
                C[(long)(r + 8) * N + col]     = v2;
                C[(long)(r + 8) * N + col + 1] = v3;
            }
        }
    }
}

// ---------------------------------------------------------------------------
// _H epilogue (exact replication of reference index gymnastics).
// ---------------------------------------------------------------------------
__global__ void k_h(const float* __restrict__ q, const float* __restrict__ w,
                    float* __restrict__ hq) {
    const int i  = blockIdx.x;   // 0..31
    const int l2 = threadIdx.x;  // 0..255
    __shared__ int   s_ind[LL];
    __shared__ float s_sel[LL * 4];

    const int rsel = l2 >> 6;
    const int lb   = (l2 & 63) * 4;

    const float w0 = w[(i * LL + l2) * RR + 0];
    const float w1 = w[(i * LL + l2) * RR + 1];
    const float w2 = w[(i * LL + l2) * RR + 2];
    const float w3 = w[(i * LL + l2) * RR + 3];

    float best = -3.402823466e38f;
    int bk = 0;
    const int nb = (64 * i) & 511;
    for (int k = 0; k < 64; ++k) {
        int n  = (nb + k) & 511;
        int bp = n >> 4, a = n & 15;
        int sbp = (bp >> 2) + ((bp & 3) << 3);
        const float* qp = q + ((long)(sbp * LL + lb) * AA + a) * RR + rsel;
        float u = qp[0] * w0 + qp[64] * w1 + qp[128] * w2 + qp[192] * w3;
        if (u > best) { best = u; bk = k; }
    }
    s_ind[l2] = bk;
    {
        int n  = (nb + bk) & 511;
        int bp = n >> 4, a = n & 15;
        int sbp = (bp >> 2) + ((bp & 3) << 3);
        const float* qp = q + ((long)(sbp * LL + lb) * AA + a) * RR + rsel;
        s_sel[l2 * 4 + 0] = qp[0];
        s_sel[l2 * 4 + 1] = qp[64];
        s_sel[l2 * 4 + 2] = qp[128];
        s_sel[l2 * 4 + 3] = qp[192];
    }
    __syncthreads();

    int key = bk, pos = 0;
    for (int j = 0; j < LL; ++j) {
        int kj = s_ind[j];
        pos += (kj < key) || (kj == key && j < l2);
    }
    float* o = hq + (long)(i * LL + pos) * 4;
    o[0] = s_sel[l2 * 4 + 0];
    o[1] = s_sel[l2 * 4 + 1];
    o[2] = s_sel[l2 * 4 + 2];
    o[3] = s_sel[l2 * 4 + 3];
}

// ---------------------------------------------------------------------------
// Launch
// ---------------------------------------------------------------------------
extern "C" void kernel_launch(void* const* d_in, const int* in_sizes, int n_in,
                              void* d_out, int out_size) {
    const float* state = (const float*)d_in[0];
    const float* pref  = (const float*)d_in[1];
    const float* W1 = (const float*)d_in[3];
    const float* b1 = (const float*)d_in[4];
    const float* W2 = (const float*)d_in[5];
    const float* b2 = (const float*)d_in[6];
    const float* W3 = (const float*)d_in[7];
    const float* b3 = (const float*)d_in[8];
    const float* W4 = (const float*)d_in[9];
    const float* b4 = (const float*)d_in[10];
    const float* W5 = (const float*)d_in[11];
    const float* b5 = (const float*)d_in[12];

    float* out = (float*)d_out;
    float* hq  = out;                        // [8192, 4]
    float* q   = out + BB * LL * RR;         // [32, 256, 16, 4]

    float *x0, *a1, *a2, *a3, *a4;
    cudaGetSymbolAddress((void**)&x0, g_x0);
    cudaGetSymbolAddress((void**)&a1, g_a1);
    cudaGetSymbolAddress((void**)&a2, g_a2);
    cudaGetSymbolAddress((void**)&a3, g_a3);
    cudaGetSymbolAddress((void**)&a4, g_a4);

    cudaFuncSetAttribute(k_gemm<true>,  cudaFuncAttributeMaxDynamicSharedMemorySize, SMB);
    cudaFuncSetAttribute(k_gemm<false>, cudaFuncAttributeMaxDynamicSharedMemorySize, SMB);

    k_concat<<<(M_TOK * K0P + 255) / 256, 256>>>(state, pref, x0);

    {
        dim3 g((D1 + 127) / 128, M_TOK / 128);
        k_gemm<true><<<g, 256, SMB>>>(x0, W1, b1, a1, D1, K0P, K0);
    }
    {
        dim3 g((D2 + 127) / 128, M_TOK / 128);
        k_gemm<true><<<g, 256, SMB>>>(a1, W2, b2, a2, D2, D1, D1);
    }
    {
        dim3 g((D3 + 127) / 128, M_TOK / 128);
        k_gemm<true><<<g, 256, SMB>>>(a2, W3, b3, a3, D3, D2, D2);
    }
    {
        dim3 g((D4 + 127) / 128, M_TOK / 128);
        k_gemm<true><<<g, 256, SMB>>>(a3, W4, b4, a4, D4, D3, D3);
    }
    {
        dim3 g(1, M_TOK / 128);
        k_gemm<false><<<g, 256, SMB>>>(a4, W5, b5, q, D5, D4, D4);
    }

    k_h<<<BB, LL>>>(q, pref, hq);
}